// round 4
// baseline (speedup 1.0000x reference)
#include <cuda_runtime.h>
#include <cuda_bf16.h>
#include <math.h>
#include <cstdint>

#define NN   8192
#define DIN  256
#define DOUT 128

// ---------------- scratch ----------------
__device__ float g_h[NN * DOUT];                 // 4 MB fp32 h
__device__ float g_a1[NN], g_a2[NN];
__device__ float g_e1p[NN], g_e1n[NN];           // exp(a1), exp(0.01*a1)
__device__ float g_e2p[NN], g_e2n[NN];           // exp(a2), exp(0.01*a2)
__device__ unsigned short g_hT_hi[DOUT * NN];    // bf16 hT hi  [d][j]
__device__ unsigned short g_hT_lo[DOUT * NN];    // bf16 hT lo  [d][j]

// ---------------- helpers ----------------
__device__ __forceinline__ uint32_t smem_u32(const void* p) {
    uint32_t a;
    asm("{ .reg .u64 t; cvta.to.shared.u64 t, %1; cvt.u32.u64 %0, t; }" : "=r"(a) : "l"(p));
    return a;
}
__device__ __forceinline__ uint32_t pack_bf16x2(float lo, float hi) {
    uint32_t r;
    asm("cvt.rn.bf16x2.f32 %0, %1, %2;" : "=r"(r) : "f"(hi), "f"(lo));
    return r;
}
#define LDSM4(r0, r1, r2, r3, addr)                                            \
    asm volatile("ldmatrix.sync.aligned.m8n8.x4.shared.b16 {%0,%1,%2,%3}, [%4];" \
        : "=r"(r0), "=r"(r1), "=r"(r2), "=r"(r3) : "r"(addr))
#define MMA_BF16(c, a, b0, b1)                                                 \
    asm volatile("mma.sync.aligned.m16n8k16.row.col.f32.bf16.bf16.f32 "        \
        "{%0,%1,%2,%3},{%4,%5,%6,%7},{%8,%9},{%0,%1,%2,%3};"                   \
        : "+f"((c)[0]), "+f"((c)[1]), "+f"((c)[2]), "+f"((c)[3])               \
        : "r"((a)[0]), "r"((a)[1]), "r"((a)[2]), "r"((a)[3]), "r"(b0), "r"(b1))
#define CP16(dst, src)                                                         \
    asm volatile("cp.async.cg.shared.global [%0], [%1], 16;"                   \
        :: "r"(dst), "l"(src) : "memory")
#define CP_COMMIT() asm volatile("cp.async.commit_group;" ::: "memory")
#define CP_WAIT0()  asm volatile("cp.async.wait_group 0;" ::: "memory")

// ============================================================
// Kernel 1: h = feat @ W^T + b
// ============================================================
__global__ __launch_bounds__(256) void gemm_h_kernel(
    const float* __restrict__ feat, const float* __restrict__ W, const float* __restrict__ bias)
{
    __shared__ float fs[64][32];
    __shared__ float ws[32][132];
    const int t = threadIdx.x;
    const int i0 = blockIdx.x * 64;
    const int ty = t >> 4, tx = t & 15;
    float acc[4][8];
#pragma unroll
    for (int r = 0; r < 4; r++)
#pragma unroll
        for (int c = 0; c < 8; c++) acc[r][c] = 0.f;

    for (int k0 = 0; k0 < DIN; k0 += 32) {
#pragma unroll
        for (int v = 0; v < 2; v++) {
            int f = v * 256 + t, row = f >> 3, off = (f & 7) * 4;
            *(float4*)&fs[row][off] = *(const float4*)&feat[(size_t)(i0 + row) * DIN + k0 + off];
        }
        {
            int c = t >> 1, half = (t & 1) * 16;
#pragma unroll
            for (int q = 0; q < 4; q++) {
                float4 wv = *(const float4*)&W[(size_t)c * DIN + k0 + half + q * 4];
                ws[half + q * 4 + 0][c] = wv.x; ws[half + q * 4 + 1][c] = wv.y;
                ws[half + q * 4 + 2][c] = wv.z; ws[half + q * 4 + 3][c] = wv.w;
            }
        }
        __syncthreads();
#pragma unroll
        for (int kk = 0; kk < 32; kk++) {
            float a[4];
#pragma unroll
            for (int r = 0; r < 4; r++) a[r] = fs[ty * 4 + r][kk];
            float4 b0 = *(const float4*)&ws[kk][tx * 8];
            float4 b1 = *(const float4*)&ws[kk][tx * 8 + 4];
            float bb[8] = {b0.x, b0.y, b0.z, b0.w, b1.x, b1.y, b1.z, b1.w};
#pragma unroll
            for (int r = 0; r < 4; r++)
#pragma unroll
                for (int c = 0; c < 8; c++) acc[r][c] += a[r] * bb[c];
        }
        __syncthreads();
    }
#pragma unroll
    for (int r = 0; r < 4; r++) {
        int gi = i0 + ty * 4 + r;
#pragma unroll
        for (int c = 0; c < 8; c++)
            g_h[(size_t)gi * DOUT + tx * 8 + c] = acc[r][c] + bias[tx * 8 + c];
    }
}

// ============================================================
// Kernel 2: a1,a2 + factorized exp tables
// ============================================================
__global__ __launch_bounds__(256) void prep_kernel(
    const float* __restrict__ w1, const float* __restrict__ b1,
    const float* __restrict__ w2, const float* __restrict__ b2)
{
    const int warp = threadIdx.x >> 5, lane = threadIdx.x & 31;
    const int i = blockIdx.x * 8 + warp;
    float s1 = 0.f, s2 = 0.f;
#pragma unroll
    for (int d = lane; d < DOUT; d += 32) {
        float hv = g_h[(size_t)i * DOUT + d];
        s1 += hv * w1[d]; s2 += hv * w2[d];
    }
#pragma unroll
    for (int o = 16; o > 0; o >>= 1) {
        s1 += __shfl_xor_sync(0xffffffffu, s1, o);
        s2 += __shfl_xor_sync(0xffffffffu, s2, o);
    }
    if (lane == 0) {
        float a1 = s1 + b1[0], a2 = s2 + b2[0];
        g_a1[i] = a1; g_a2[i] = a2;
        g_e1p[i] = expf(a1); g_e1n[i] = expf(0.01f * a1);
        g_e2p[i] = expf(a2); g_e2n[i] = expf(0.01f * a2);
    }
}

// ============================================================
// Kernel 3: transpose + bf16 hi/lo split of h -> g_hT_hi/lo [d][j]
// ============================================================
__global__ __launch_bounds__(256) void convert_hT_kernel()
{
    __shared__ float s[32][33];
    const int i0 = blockIdx.x * 32, d0 = blockIdx.y * 32;
    const int lx = threadIdx.x & 31, ly = threadIdx.x >> 5;
#pragma unroll
    for (int q = 0; q < 4; q++) {
        int il = ly + q * 8;
        s[il][lx] = g_h[(size_t)(i0 + il) * DOUT + d0 + lx];
    }
    __syncthreads();
#pragma unroll
    for (int q = 0; q < 4; q++) {
        int dl = ly + q * 8;
        float v = s[lx][dl];
        uint32_t u = __float_as_uint(v);
        float hi = __uint_as_float(u & 0xffff0000u);
        float lo = v - hi;
        __nv_bfloat16 bl = __float2bfloat16(lo);
        size_t idx = (size_t)(d0 + dl) * NN + i0 + lx;
        g_hT_hi[idx] = (unsigned short)(u >> 16);
        g_hT_lo[idx] = *reinterpret_cast<unsigned short*>(&bl);
    }
}

// ============================================================
// Kernel 4: fused attention, 1-barrier pipelined ldmatrix+mma.sync
// 128 blocks x 256 threads; CTA M=64 x N=128, KT=64, warp tile m32n32
// ============================================================
#define KT      64
#define ITERS   (NN / KT)
#define A_HI    0
#define A_LO    8192
#define B_HI    16384
#define B_LO    32768
#define BUFS    49152
#define ATTN_SMEM (2 * BUFS)

__global__ __launch_bounds__(256) void attn_mma_kernel(
    const int* __restrict__ adj, float* __restrict__ out)
{
    extern __shared__ char smem[];
    __shared__ float den_s[64];
    const uint32_t sb = smem_u32(smem);
    const int t = threadIdx.x, lane = t & 31, wid = t >> 5;
    const int i0 = blockIdx.x * 64;

    // ---- weight-gen mapping: rows rq+16u (u<4), j's jq*4..+3 ----
    const int jq = t & 15, rq = t >> 4;
    float a1r[4], e1pv[4], e1nv[4], den[4];
    const int* adjp[4];
#pragma unroll
    for (int u = 0; u < 4; u++) {
        int gi = i0 + rq + 16 * u;
        a1r[u] = g_a1[gi]; e1pv[u] = g_e1p[gi]; e1nv[u] = g_e1n[gi];
        den[u] = 0.f;
        adjp[u] = adj + (size_t)gi * NN + jq * 4;
    }
    // ---- A STS offsets ----
    uint32_t aSts[4];
#pragma unroll
    for (int u = 0; u < 4; u++) {
        int row = rq + 16 * u;
        aSts[u] = row * 128 + ((jq * 8) ^ ((row & 7) << 4));
    }

    // ---- B cp.async mapping: row bn (=d), half bhalf ----
    const int bn = t >> 1, bhalf = t & 1;
    const unsigned short* srcH = g_hT_hi + (size_t)bn * NN + bhalf * 32;
    const unsigned short* srcL = g_hT_lo + (size_t)bn * NN + bhalf * 32;
    uint32_t bOff[4];
#pragma unroll
    for (int q = 0; q < 4; q++)
        bOff[q] = bn * 128 + ((bhalf * 64 + q * 16) ^ ((bn & 7) << 4));

    // ---- mma mapping ----
    const int wm = wid >> 2, wn = wid & 3;
    uint32_t aRowOff[2], bRowOff[2];
#pragma unroll
    for (int m = 0; m < 2; m++)
        aRowOff[m] = (uint32_t)(wm * 32 + m * 16 + (lane & 15)) * 128;
#pragma unroll
    for (int p = 0; p < 2; p++)
        bRowOff[p] = (uint32_t)(wn * 32 + p * 16 + (lane & 7) + ((lane >> 4) << 3)) * 128;
    const uint32_t mXor = (lane & 7) << 4;
    const uint32_t aCol = (lane >> 4) << 4;
    const uint32_t bCol = (lane & 8) << 1;

    float acc[32];
#pragma unroll
    for (int i = 0; i < 32; i++) acc[i] = 0.f;

    // ---- pipeline registers ----
    int4 adjR[4];                 // adj for tile (k+1)
    float4 a2R, epR, enR;         // exps for tile (k+1)
    uint2 whi[4], wlo[4];         // weights for tile k (ready to STS)

    auto ldExps = [&](int J0) {
        a2R = *(const float4*)&g_a2[J0 + jq * 4];
        epR = *(const float4*)&g_e2p[J0 + jq * 4];
        enR = *(const float4*)&g_e2n[J0 + jq * 4];
    };
    auto wQuarter = [&](int u) {
        float a2a[4] = {a2R.x, a2R.y, a2R.z, a2R.w};
        float epa[4] = {epR.x, epR.y, epR.z, epR.w};
        float ena[4] = {enR.x, enR.y, enR.z, enR.w};
        int avi[4] = {adjR[u].x, adjR[u].y, adjR[u].z, adjR[u].w};
        float w[4];
#pragma unroll
        for (int q = 0; q < 4; q++) {
            float ta = a1r[u] + a2a[q];
            float e1 = (ta >= 0.f) ? e1pv[u] : e1nv[u];
            float e2 = (ta >= 0.f) ? epa[q] : ena[q];
            float wq = e1 * e2;
            wq = avi[q] ? wq : 0.f;
            den[u] += wq;
            w[q] = wq;
        }
        uint32_t u0 = __float_as_uint(w[0]), u1 = __float_as_uint(w[1]);
        uint32_t u2 = __float_as_uint(w[2]), u3 = __float_as_uint(w[3]);
        whi[u] = make_uint2(__byte_perm(u0, u1, 0x7632), __byte_perm(u2, u3, 0x7632));
        float l0 = w[0] - __uint_as_float(u0 & 0xffff0000u);
        float l1 = w[1] - __uint_as_float(u1 & 0xffff0000u);
        float l2 = w[2] - __uint_as_float(u2 & 0xffff0000u);
        float l3 = w[3] - __uint_as_float(u3 & 0xffff0000u);
        wlo[u] = make_uint2(pack_bf16x2(l0, l1), pack_bf16x2(l2, l3));
    };
    auto cpB = [&](uint32_t bufb, int J0) {
        const unsigned short* sH = srcH + J0;
        const unsigned short* sL = srcL + J0;
#pragma unroll
        for (int q = 0; q < 4; q++) {
            CP16(sb + bufb + B_HI + bOff[q], (const void*)(sH + q * 8));
            CP16(sb + bufb + B_LO + bOff[q], (const void*)(sL + q * 8));
        }
        CP_COMMIT();
    };

    // ---- prologue: tile 0 ----
#pragma unroll
    for (int u = 0; u < 4; u++) adjR[u] = *(const int4*)(adjp[u]);
    ldExps(0);
    cpB(0, 0);
#pragma unroll
    for (int u = 0; u < 4; u++) wQuarter(u);   // w(0)
#pragma unroll
    for (int u = 0; u < 4; u++) adjR[u] = *(const int4*)(adjp[u] + KT);
    ldExps(KT);

    for (int k = 0; k < ITERS; k++) {
        const uint32_t bufb = (k & 1) ? BUFS : 0;
        const uint32_t obufb = BUFS - bufb;
        // serial section: STS A(k) + wait B(k) + barrier
#pragma unroll
        for (int u = 0; u < 4; u++) {
            *(uint2*)(smem + bufb + A_HI + aSts[u]) = whi[u];
            *(uint2*)(smem + bufb + A_LO + aSts[u]) = wlo[u];
        }
        CP_WAIT0();
        __syncthreads();

        if (k + 1 < ITERS) cpB(obufb, (k + 1) * KT);

        const uint32_t ab = sb + bufb;
#pragma unroll
        for (int s = 0; s < 4; s++) {
            const uint32_t cs = s * 32;
            uint32_t ah[2][4], al[2][4], bh[2][4], bl[2][4];
            const uint32_t ca = (cs + aCol) ^ mXor;
            const uint32_t cb = (cs + bCol) ^ mXor;
#pragma unroll
            for (int m = 0; m < 2; m++) {
                LDSM4(ah[m][0], ah[m][1], ah[m][2], ah[m][3], ab + A_HI + aRowOff[m] + ca);
                LDSM4(al[m][0], al[m][1], al[m][2], al[m][3], ab + A_LO + aRowOff[m] + ca);
            }
#pragma unroll
            for (int p = 0; p < 2; p++) {
                LDSM4(bh[p][0], bh[p][1], bh[p][2], bh[p][3], ab + B_HI + bRowOff[p] + cb);
                LDSM4(bl[p][0], bl[p][1], bl[p][2], bl[p][3], ab + B_LO + bRowOff[p] + cb);
            }
            // interleaved weight-gen for tile k+1 (quarter s) + adj prefetch k+2
            if (k + 1 < ITERS) {
                wQuarter(s);
                if (k + 2 < ITERS) adjR[s] = *(const int4*)(adjp[s] + (k + 2) * KT);
            }
#pragma unroll
            for (int m = 0; m < 2; m++)
#pragma unroll
                for (int nt = 0; nt < 4; nt++) {
                    float* c = &acc[(m * 4 + nt) * 4];
                    uint32_t b0 = bh[nt >> 1][(nt & 1) * 2], b1 = bh[nt >> 1][(nt & 1) * 2 + 1];
                    MMA_BF16(c, ah[m], b0, b1);
                    MMA_BF16(c, al[m], b0, b1);
                    uint32_t d0 = bl[nt >> 1][(nt & 1) * 2], d1 = bl[nt >> 1][(nt & 1) * 2 + 1];
                    MMA_BF16(c, ah[m], d0, d1);
                }
        }
        if (k + 2 < ITERS) ldExps((k + 2) * KT);
    }

    // ---- denominator reduce over jq (16 lanes) ----
#pragma unroll
    for (int o = 8; o > 0; o >>= 1)
#pragma unroll
        for (int u = 0; u < 4; u++) den[u] += __shfl_xor_sync(0xffffffffu, den[u], o);
    if (jq == 0)
#pragma unroll
        for (int u = 0; u < 4; u++) den_s[rq + 16 * u] = den[u];
    __syncthreads();

    // ---- epilogue ----
#pragma unroll
    for (int m = 0; m < 2; m++) {
        int r0 = wm * 32 + m * 16 + (lane >> 2);
        float inv0 = 1.0f / den_s[r0];
        float inv1 = 1.0f / den_s[r0 + 8];
#pragma unroll
        for (int nt = 0; nt < 4; nt++) {
            float* c = &acc[(m * 4 + nt) * 4];
            int col = wn * 32 + nt * 8 + (lane & 3) * 2;
            *(float2*)&out[(size_t)(i0 + r0) * DOUT + col]     = make_float2(c[0] * inv0, c[1] * inv0);
            *(float2*)&out[(size_t)(i0 + r0 + 8) * DOUT + col] = make_float2(c[2] * inv1, c[3] * inv1);
        }
    }
}

// ============================================================
extern "C" void kernel_launch(void* const* d_in, const int* in_sizes, int n_in,
                              void* d_out, int out_size)
{
    const float* feat = (const float*)d_in[0];
    const int*   adj  = (const int*)d_in[1];
    const float* W    = (const float*)d_in[2];
    const float* b    = (const float*)d_in[3];
    const float* w1   = (const float*)d_in[4];
    const float* b1   = (const float*)d_in[5];
    const float* w2   = (const float*)d_in[6];
    const float* b2   = (const float*)d_in[7];
    float* out = (float*)d_out;

    static bool attr_set = false;
    if (!attr_set) {
        cudaFuncSetAttribute(attn_mma_kernel,
                             cudaFuncAttributeMaxDynamicSharedMemorySize, ATTN_SMEM);
        attr_set = true;
    }

    gemm_h_kernel<<<NN / 64, 256>>>(feat, W, b);
    prep_kernel<<<NN / 8, 256>>>(w1, b1, w2, b2);
    convert_hT_kernel<<<dim3(NN / 32, DOUT / 32), 256>>>();
    attn_mma_kernel<<<NN / 64, 256, ATTN_SMEM>>>(adj, out);
}

// round 5
// speedup vs baseline: 1.6074x; 1.6074x over previous
#include <cuda_runtime.h>
#include <cuda_bf16.h>
#include <math.h>
#include <cstdint>

#define NN   8192
#define DIN  256
#define DOUT 128

// ---------------- scratch ----------------
__device__ float g_h[NN * DOUT];                 // 4 MB fp32 h
__device__ float g_a1[NN], g_a2[NN];
__device__ float g_e1p[NN], g_e1n[NN];           // exp(a1), exp(0.01*a1)
__device__ float g_e2p[NN], g_e2n[NN];           // exp(a2), exp(0.01*a2)
__device__ unsigned short g_hT_hi[DOUT * NN];    // bf16 hT hi  [d][j]
__device__ unsigned short g_hT_lo[DOUT * NN];    // bf16 hT lo  [d][j]

// ---------------- helpers ----------------
__device__ __forceinline__ uint32_t smem_u32(const void* p) {
    uint32_t a;
    asm("{ .reg .u64 t; cvta.to.shared.u64 t, %1; cvt.u32.u64 %0, t; }" : "=r"(a) : "l"(p));
    return a;
}
__device__ __forceinline__ uint32_t pack_bf16x2(float lo, float hi) {
    uint32_t r;
    asm("cvt.rn.bf16x2.f32 %0, %1, %2;" : "=r"(r) : "f"(hi), "f"(lo));
    return r;
}
#define LDSM4(r0, r1, r2, r3, addr)                                            \
    asm volatile("ldmatrix.sync.aligned.m8n8.x4.shared.b16 {%0,%1,%2,%3}, [%4];" \
        : "=r"(r0), "=r"(r1), "=r"(r2), "=r"(r3) : "r"(addr))
#define MMA_BF16(c, a, b0, b1)                                                 \
    asm volatile("mma.sync.aligned.m16n8k16.row.col.f32.bf16.bf16.f32 "        \
        "{%0,%1,%2,%3},{%4,%5,%6,%7},{%8,%9},{%0,%1,%2,%3};"                   \
        : "+f"((c)[0]), "+f"((c)[1]), "+f"((c)[2]), "+f"((c)[3])               \
        : "r"((a)[0]), "r"((a)[1]), "r"((a)[2]), "r"((a)[3]), "r"(b0), "r"(b1))

// ============================================================
// Kernel 1: h = feat @ W^T + b
// ============================================================
__global__ __launch_bounds__(256) void gemm_h_kernel(
    const float* __restrict__ feat, const float* __restrict__ W, const float* __restrict__ bias)
{
    __shared__ float fs[64][32];
    __shared__ float ws[32][132];
    const int t = threadIdx.x;
    const int i0 = blockIdx.x * 64;
    const int ty = t >> 4, tx = t & 15;
    float acc[4][8];
#pragma unroll
    for (int r = 0; r < 4; r++)
#pragma unroll
        for (int c = 0; c < 8; c++) acc[r][c] = 0.f;

    for (int k0 = 0; k0 < DIN; k0 += 32) {
#pragma unroll
        for (int v = 0; v < 2; v++) {
            int f = v * 256 + t, row = f >> 3, off = (f & 7) * 4;
            *(float4*)&fs[row][off] = *(const float4*)&feat[(size_t)(i0 + row) * DIN + k0 + off];
        }
        {
            int c = t >> 1, half = (t & 1) * 16;
#pragma unroll
            for (int q = 0; q < 4; q++) {
                float4 wv = *(const float4*)&W[(size_t)c * DIN + k0 + half + q * 4];
                ws[half + q * 4 + 0][c] = wv.x; ws[half + q * 4 + 1][c] = wv.y;
                ws[half + q * 4 + 2][c] = wv.z; ws[half + q * 4 + 3][c] = wv.w;
            }
        }
        __syncthreads();
#pragma unroll
        for (int kk = 0; kk < 32; kk++) {
            float a[4];
#pragma unroll
            for (int r = 0; r < 4; r++) a[r] = fs[ty * 4 + r][kk];
            float4 b0 = *(const float4*)&ws[kk][tx * 8];
            float4 b1 = *(const float4*)&ws[kk][tx * 8 + 4];
            float bb[8] = {b0.x, b0.y, b0.z, b0.w, b1.x, b1.y, b1.z, b1.w};
#pragma unroll
            for (int r = 0; r < 4; r++)
#pragma unroll
                for (int c = 0; c < 8; c++) acc[r][c] += a[r] * bb[c];
        }
        __syncthreads();
    }
#pragma unroll
    for (int r = 0; r < 4; r++) {
        int gi = i0 + ty * 4 + r;
#pragma unroll
        for (int c = 0; c < 8; c++)
            g_h[(size_t)gi * DOUT + tx * 8 + c] = acc[r][c] + bias[tx * 8 + c];
    }
}

// ============================================================
// Kernel 2: a1,a2 + factorized exp tables
// ============================================================
__global__ __launch_bounds__(256) void prep_kernel(
    const float* __restrict__ w1, const float* __restrict__ b1,
    const float* __restrict__ w2, const float* __restrict__ b2)
{
    const int warp = threadIdx.x >> 5, lane = threadIdx.x & 31;
    const int i = blockIdx.x * 8 + warp;
    float s1 = 0.f, s2 = 0.f;
#pragma unroll
    for (int d = lane; d < DOUT; d += 32) {
        float hv = g_h[(size_t)i * DOUT + d];
        s1 += hv * w1[d]; s2 += hv * w2[d];
    }
#pragma unroll
    for (int o = 16; o > 0; o >>= 1) {
        s1 += __shfl_xor_sync(0xffffffffu, s1, o);
        s2 += __shfl_xor_sync(0xffffffffu, s2, o);
    }
    if (lane == 0) {
        float a1 = s1 + b1[0], a2 = s2 + b2[0];
        g_a1[i] = a1; g_a2[i] = a2;
        g_e1p[i] = expf(a1); g_e1n[i] = expf(0.01f * a1);
        g_e2p[i] = expf(a2); g_e2n[i] = expf(0.01f * a2);
    }
}

// ============================================================
// Kernel 3: transpose + bf16 hi/lo split of h -> g_hT_hi/lo [d][j]
// ============================================================
__global__ __launch_bounds__(256) void convert_hT_kernel()
{
    __shared__ float s[32][33];
    const int i0 = blockIdx.x * 32, d0 = blockIdx.y * 32;
    const int lx = threadIdx.x & 31, ly = threadIdx.x >> 5;
#pragma unroll
    for (int q = 0; q < 4; q++) {
        int il = ly + q * 8;
        s[il][lx] = g_h[(size_t)(i0 + il) * DOUT + d0 + lx];
    }
    __syncthreads();
#pragma unroll
    for (int q = 0; q < 4; q++) {
        int dl = ly + q * 8;
        float v = s[lx][dl];
        uint32_t u = __float_as_uint(v);
        float hi = __uint_as_float(u & 0xffff0000u);
        float lo = v - hi;
        __nv_bfloat16 bl = __float2bfloat16(lo);
        size_t idx = (size_t)(d0 + dl) * NN + i0 + lx;
        g_hT_hi[idx] = (unsigned short)(u >> 16);
        g_hT_lo[idx] = *reinterpret_cast<unsigned short*>(&bl);
    }
}

// ============================================================
// Kernel 4: fused attention, ldmatrix+mma.sync, 512 threads
// 128 blocks; CTA M=64 x N=128, KT=64.
// 16 warps = 2 k-teams x (2m x 4n); team0 ksteps{0,1}, team1 {2,3}.
// SMEM per buf: A_hi 8K | A_lo 8K | B_hi 16K | B_lo 16K = 48K; x2 = 96K
// ============================================================
#define KT      64
#define ITERS   (NN / KT)
#define A_HI    0
#define A_LO    8192
#define B_HI    16384
#define B_LO    32768
#define BUFS    49152
#define ATTN_SMEM (2 * BUFS)

__global__ __launch_bounds__(512) void attn_mma_kernel(
    const int* __restrict__ adj, float* __restrict__ out)
{
    extern __shared__ char smem[];
    __shared__ float den_s[64];
    const uint32_t sb = smem_u32(smem);
    const int t = threadIdx.x, lane = t & 31, wid = t >> 5;
    const int i0 = blockIdx.x * 64;

    // ---- weight-gen mapping: rows rq, rq+32; j's jq*4..+3 ----
    const int jq = t & 15, rq = (t >> 4) & 31;
    float a1r[2], e1pv[2], e1nv[2], den[2];
    const int* adjp[2];
    uint32_t aSts[2];
#pragma unroll
    for (int u = 0; u < 2; u++) {
        int row = rq + 32 * u;
        int gi = i0 + row;
        a1r[u] = g_a1[gi]; e1pv[u] = g_e1p[gi]; e1nv[u] = g_e1n[gi];
        den[u] = 0.f;
        adjp[u] = adj + (size_t)gi * NN + jq * 4;
        aSts[u] = row * 128 + ((jq * 8) ^ ((row & 7) << 4));
    }

    // ---- B copy mapping: row bn (=d), quarter bq (16 j = 32B) ----
    const int bn = t >> 2, bq = t & 3;
    const unsigned short* srcH = g_hT_hi + (size_t)bn * NN + bq * 16;
    const unsigned short* srcL = g_hT_lo + (size_t)bn * NN + bq * 16;
    uint32_t bOff[2];
#pragma unroll
    for (int q = 0; q < 2; q++)
        bOff[q] = bn * 128 + (((uint32_t)(bq * 32 + q * 16)) ^ ((bn & 7) << 4));

    // ---- mma mapping ----
    const int team = wid >> 3, w8 = wid & 7;
    const int wm = w8 >> 2, wn = w8 & 3;
    const int s0 = team * 2;
    uint32_t aRowOff[2], bRowOff[2];
#pragma unroll
    for (int m = 0; m < 2; m++)
        aRowOff[m] = (uint32_t)(wm * 32 + m * 16 + (lane & 15)) * 128;
#pragma unroll
    for (int p = 0; p < 2; p++)
        bRowOff[p] = (uint32_t)(wn * 32 + p * 16 + (lane & 7) + ((lane >> 4) << 3)) * 128;
    const uint32_t mXor = (lane & 7) << 4;
    const uint32_t aCol = (lane >> 4) << 4;
    const uint32_t bCol = (lane & 8) << 1;

    float acc[32];
#pragma unroll
    for (int i = 0; i < 32; i++) acc[i] = 0.f;

    // ---- prefetch regs ----
    int4 adjR[2]; uint4 hHR[2], hLR[2]; float4 a2R, epR, enR;
    auto prefetch = [&](int J0) {
#pragma unroll
        for (int u = 0; u < 2; u++) adjR[u] = *(const int4*)(adjp[u] + J0);
#pragma unroll
        for (int q = 0; q < 2; q++) {
            hHR[q] = ((const uint4*)(srcH + J0))[q];
            hLR[q] = ((const uint4*)(srcL + J0))[q];
        }
        a2R = *(const float4*)&g_a2[J0 + jq * 4];
        epR = *(const float4*)&g_e2p[J0 + jq * 4];
        enR = *(const float4*)&g_e2n[J0 + jq * 4];
    };
    prefetch(0);

    for (int k = 0; k < ITERS; k++) {
        const uint32_t bufb = (k & 1) ? BUFS : 0;
        __syncthreads();   // protect previous iteration's reads of this buffer

        // ---- STS B (hi/lo) from prefetched regs ----
#pragma unroll
        for (int q = 0; q < 2; q++) {
            *(uint4*)(smem + bufb + B_HI + bOff[q]) = hHR[q];
            *(uint4*)(smem + bufb + B_LO + bOff[q]) = hLR[q];
        }
        // ---- weights: compute, split, STS A ----
        {
            float a2a[4] = {a2R.x, a2R.y, a2R.z, a2R.w};
            float epa[4] = {epR.x, epR.y, epR.z, epR.w};
            float ena[4] = {enR.x, enR.y, enR.z, enR.w};
#pragma unroll
            for (int u = 0; u < 2; u++) {
                int avi[4] = {adjR[u].x, adjR[u].y, adjR[u].z, adjR[u].w};
                float w[4];
#pragma unroll
                for (int q = 0; q < 4; q++) {
                    float ta = a1r[u] + a2a[q];
                    float e1 = (ta >= 0.f) ? e1pv[u] : e1nv[u];
                    float e2 = (ta >= 0.f) ? epa[q] : ena[q];
                    float wq = e1 * e2;
                    wq = avi[q] ? wq : 0.f;
                    den[u] += wq;
                    w[q] = wq;
                }
                uint32_t u0 = __float_as_uint(w[0]), u1 = __float_as_uint(w[1]);
                uint32_t u2 = __float_as_uint(w[2]), u3 = __float_as_uint(w[3]);
                uint32_t hi0 = __byte_perm(u0, u1, 0x7632);
                uint32_t hi1 = __byte_perm(u2, u3, 0x7632);
                float l0 = w[0] - __uint_as_float(u0 & 0xffff0000u);
                float l1 = w[1] - __uint_as_float(u1 & 0xffff0000u);
                float l2 = w[2] - __uint_as_float(u2 & 0xffff0000u);
                float l3 = w[3] - __uint_as_float(u3 & 0xffff0000u);
                uint32_t lo0 = pack_bf16x2(l0, l1);
                uint32_t lo1 = pack_bf16x2(l2, l3);
                *(uint2*)(smem + bufb + A_HI + aSts[u]) = make_uint2(hi0, hi1);
                *(uint2*)(smem + bufb + A_LO + aSts[u]) = make_uint2(lo0, lo1);
            }
        }
        __syncthreads();

        // ---- prefetch next tile (LDGs overlap MMA) ----
        if (k + 1 < ITERS) prefetch((k + 1) * KT);

        // ---- mma: this team's 2 k16 steps ----
        const uint32_t ab = sb + bufb;
#pragma unroll
        for (int si = 0; si < 2; si++) {
            const uint32_t cs = (s0 + si) * 32;
            uint32_t ah[2][4], al[2][4], bh[2][4], bl[2][4];
            const uint32_t ca = (cs + aCol) ^ mXor;
            const uint32_t cb = (cs + bCol) ^ mXor;
#pragma unroll
            for (int m = 0; m < 2; m++) {
                LDSM4(ah[m][0], ah[m][1], ah[m][2], ah[m][3], ab + A_HI + aRowOff[m] + ca);
                LDSM4(al[m][0], al[m][1], al[m][2], al[m][3], ab + A_LO + aRowOff[m] + ca);
            }
#pragma unroll
            for (int p = 0; p < 2; p++) {
                LDSM4(bh[p][0], bh[p][1], bh[p][2], bh[p][3], ab + B_HI + bRowOff[p] + cb);
                LDSM4(bl[p][0], bl[p][1], bl[p][2], bl[p][3], ab + B_LO + bRowOff[p] + cb);
            }
#pragma unroll
            for (int m = 0; m < 2; m++)
#pragma unroll
                for (int nt = 0; nt < 4; nt++) {
                    float* c = &acc[(m * 4 + nt) * 4];
                    uint32_t b0 = bh[nt >> 1][(nt & 1) * 2], b1 = bh[nt >> 1][(nt & 1) * 2 + 1];
                    MMA_BF16(c, ah[m], b0, b1);
                    MMA_BF16(c, al[m], b0, b1);
                    uint32_t d0 = bl[nt >> 1][(nt & 1) * 2], d1 = bl[nt >> 1][(nt & 1) * 2 + 1];
                    MMA_BF16(c, ah[m], d0, d1);
                }
        }
    }

    // ---- denominator reduce over jq (16 lanes) ----
#pragma unroll
    for (int o = 8; o > 0; o >>= 1)
#pragma unroll
        for (int u = 0; u < 2; u++) den[u] += __shfl_xor_sync(0xffffffffu, den[u], o);
    if (jq == 0) { den_s[rq] = den[0]; den_s[rq + 32] = den[1]; }

    // ---- merge teams: team1 -> smem, team0 adds, divides, stores ----
    float* out_s = (float*)smem;   // 64 x 130 floats = 33.3 KB (buffers dead)
    __syncthreads();
    if (team == 1) {
#pragma unroll
        for (int m = 0; m < 2; m++) {
            int r0 = wm * 32 + m * 16 + (lane >> 2);
#pragma unroll
            for (int nt = 0; nt < 4; nt++) {
                float* c = &acc[(m * 4 + nt) * 4];
                int col = wn * 32 + nt * 8 + (lane & 3) * 2;
                *(float2*)&out_s[r0 * 130 + col]       = make_float2(c[0], c[1]);
                *(float2*)&out_s[(r0 + 8) * 130 + col] = make_float2(c[2], c[3]);
            }
        }
    }
    __syncthreads();
    if (team == 0) {
#pragma unroll
        for (int m = 0; m < 2; m++) {
            int r0 = wm * 32 + m * 16 + (lane >> 2);
            float inv0 = 1.0f / den_s[r0];
            float inv1 = 1.0f / den_s[r0 + 8];
#pragma unroll
            for (int nt = 0; nt < 4; nt++) {
                float* c = &acc[(m * 4 + nt) * 4];
                int col = wn * 32 + nt * 8 + (lane & 3) * 2;
                float2 p0 = *(const float2*)&out_s[r0 * 130 + col];
                float2 p1 = *(const float2*)&out_s[(r0 + 8) * 130 + col];
                *(float2*)&out[(size_t)(i0 + r0) * DOUT + col] =
                    make_float2((c[0] + p0.x) * inv0, (c[1] + p0.y) * inv0);
                *(float2*)&out[(size_t)(i0 + r0 + 8) * DOUT + col] =
                    make_float2((c[2] + p1.x) * inv1, (c[3] + p1.y) * inv1);
            }
        }
    }
}

// ============================================================
extern "C" void kernel_launch(void* const* d_in, const int* in_sizes, int n_in,
                              void* d_out, int out_size)
{
    const float* feat = (const float*)d_in[0];
    const int*   adj  = (const int*)d_in[1];
    const float* W    = (const float*)d_in[2];
    const float* b    = (const float*)d_in[3];
    const float* w1   = (const float*)d_in[4];
    const float* b1   = (const float*)d_in[5];
    const float* w2   = (const float*)d_in[6];
    const float* b2   = (const float*)d_in[7];
    float* out = (float*)d_out;

    static bool attr_set = false;
    if (!attr_set) {
        cudaFuncSetAttribute(attn_mma_kernel,
                             cudaFuncAttributeMaxDynamicSharedMemorySize, ATTN_SMEM);
        attr_set = true;
    }

    gemm_h_kernel<<<NN / 64, 256>>>(feat, W, b);
    prep_kernel<<<NN / 8, 256>>>(w1, b1, w2, b2);
    convert_hT_kernel<<<dim3(NN / 32, DOUT / 32), 256>>>();
    attn_mma_kernel<<<NN / 64, 512, ATTN_SMEM>>>(adj, out);
}

// round 6
// speedup vs baseline: 2.1034x; 1.3085x over previous
#include <cuda_runtime.h>
#include <cuda_fp16.h>
#include <math.h>
#include <cstdint>

#define NN   8192
#define DIN  256
#define DOUT 128

// ---------------- scratch ----------------
__device__ float g_h[NN * DOUT];                 // 4 MB fp32 h
__device__ float g_a1[NN], g_a2[NN];
__device__ float g_e1p[NN], g_e1n[NN];           // exp(a1), exp(0.01*a1)
__device__ float g_e2p[NN], g_e2n[NN];           // exp(a2), exp(0.01*a2)
__device__ unsigned short g_hTf[DOUT * NN];      // fp16 hT [d][j]

// ---------------- helpers ----------------
__device__ __forceinline__ uint32_t smem_u32(const void* p) {
    uint32_t a;
    asm("{ .reg .u64 t; cvta.to.shared.u64 t, %1; cvt.u32.u64 %0, t; }" : "=r"(a) : "l"(p));
    return a;
}
#define LDSM4(r0, r1, r2, r3, addr)                                            \
    asm volatile("ldmatrix.sync.aligned.m8n8.x4.shared.b16 {%0,%1,%2,%3}, [%4];" \
        : "=r"(r0), "=r"(r1), "=r"(r2), "=r"(r3) : "r"(addr))
#define MMA_F16(c, a, b0, b1)                                                  \
    asm volatile("mma.sync.aligned.m16n8k16.row.col.f32.f16.f16.f32 "          \
        "{%0,%1,%2,%3},{%4,%5,%6,%7},{%8,%9},{%0,%1,%2,%3};"                   \
        : "+f"((c)[0]), "+f"((c)[1]), "+f"((c)[2]), "+f"((c)[3])               \
        : "r"((a)[0]), "r"((a)[1]), "r"((a)[2]), "r"((a)[3]), "r"(b0), "r"(b1))
#define CP16(dst, src)                                                         \
    asm volatile("cp.async.ca.shared.global [%0], [%1], 16;"                   \
        :: "r"(dst), "l"(src) : "memory")
#define CP_COMMIT() asm volatile("cp.async.commit_group;" ::: "memory")
#define CP_WAIT0()  asm volatile("cp.async.wait_group 0;" ::: "memory")

// ============================================================
// Kernel 1: h = feat @ W^T + b
// ============================================================
__global__ __launch_bounds__(256) void gemm_h_kernel(
    const float* __restrict__ feat, const float* __restrict__ W, const float* __restrict__ bias)
{
    __shared__ float fs[64][32];
    __shared__ float ws[32][132];
    const int t = threadIdx.x;
    const int i0 = blockIdx.x * 64;
    const int ty = t >> 4, tx = t & 15;
    float acc[4][8];
#pragma unroll
    for (int r = 0; r < 4; r++)
#pragma unroll
        for (int c = 0; c < 8; c++) acc[r][c] = 0.f;

    for (int k0 = 0; k0 < DIN; k0 += 32) {
#pragma unroll
        for (int v = 0; v < 2; v++) {
            int f = v * 256 + t, row = f >> 3, off = (f & 7) * 4;
            *(float4*)&fs[row][off] = *(const float4*)&feat[(size_t)(i0 + row) * DIN + k0 + off];
        }
        {
            int c = t >> 1, half = (t & 1) * 16;
#pragma unroll
            for (int q = 0; q < 4; q++) {
                float4 wv = *(const float4*)&W[(size_t)c * DIN + k0 + half + q * 4];
                ws[half + q * 4 + 0][c] = wv.x; ws[half + q * 4 + 1][c] = wv.y;
                ws[half + q * 4 + 2][c] = wv.z; ws[half + q * 4 + 3][c] = wv.w;
            }
        }
        __syncthreads();
#pragma unroll
        for (int kk = 0; kk < 32; kk++) {
            float a[4];
#pragma unroll
            for (int r = 0; r < 4; r++) a[r] = fs[ty * 4 + r][kk];
            float4 b0 = *(const float4*)&ws[kk][tx * 8];
            float4 b1 = *(const float4*)&ws[kk][tx * 8 + 4];
            float bb[8] = {b0.x, b0.y, b0.z, b0.w, b1.x, b1.y, b1.z, b1.w};
#pragma unroll
            for (int r = 0; r < 4; r++)
#pragma unroll
                for (int c = 0; c < 8; c++) acc[r][c] += a[r] * bb[c];
        }
        __syncthreads();
    }
#pragma unroll
    for (int r = 0; r < 4; r++) {
        int gi = i0 + ty * 4 + r;
#pragma unroll
        for (int c = 0; c < 8; c++)
            g_h[(size_t)gi * DOUT + tx * 8 + c] = acc[r][c] + bias[tx * 8 + c];
    }
}

// ============================================================
// Kernel 2: a1,a2 + factorized exp tables
// ============================================================
__global__ __launch_bounds__(256) void prep_kernel(
    const float* __restrict__ w1, const float* __restrict__ b1,
    const float* __restrict__ w2, const float* __restrict__ b2)
{
    const int warp = threadIdx.x >> 5, lane = threadIdx.x & 31;
    const int i = blockIdx.x * 8 + warp;
    float s1 = 0.f, s2 = 0.f;
#pragma unroll
    for (int d = lane; d < DOUT; d += 32) {
        float hv = g_h[(size_t)i * DOUT + d];
        s1 += hv * w1[d]; s2 += hv * w2[d];
    }
#pragma unroll
    for (int o = 16; o > 0; o >>= 1) {
        s1 += __shfl_xor_sync(0xffffffffu, s1, o);
        s2 += __shfl_xor_sync(0xffffffffu, s2, o);
    }
    if (lane == 0) {
        float a1 = s1 + b1[0], a2 = s2 + b2[0];
        g_a1[i] = a1; g_a2[i] = a2;
        g_e1p[i] = expf(a1); g_e1n[i] = expf(0.01f * a1);
        g_e2p[i] = expf(a2); g_e2n[i] = expf(0.01f * a2);
    }
}

// ============================================================
// Kernel 3: transpose h -> fp16 hT [d][j]
// ============================================================
__global__ __launch_bounds__(256) void convert_hT_kernel()
{
    __shared__ float s[32][33];
    const int i0 = blockIdx.x * 32, d0 = blockIdx.y * 32;
    const int lx = threadIdx.x & 31, ly = threadIdx.x >> 5;
#pragma unroll
    for (int q = 0; q < 4; q++) {
        int il = ly + q * 8;
        s[il][lx] = g_h[(size_t)(i0 + il) * DOUT + d0 + lx];
    }
    __syncthreads();
#pragma unroll
    for (int q = 0; q < 4; q++) {
        int dl = ly + q * 8;
        __half hv = __float2half_rn(s[lx][dl]);
        g_hTf[(size_t)(d0 + dl) * NN + i0 + lx] = *reinterpret_cast<unsigned short*>(&hv);
    }
}

// ============================================================
// Kernel 4: fused attention, fp16 2-product, KT=128, 512 threads
// 128 blocks; CTA M=64 x N=128. 16 warps = 2 k-teams x (2m x 4n),
// team0 ksteps 0-3, team1 ksteps 4-7.
// SMEM/buffer: A_hi 16K | A_lo 16K | B 32K = 64K; x2 = 128K
// ============================================================
#define KT      128
#define ITERS   (NN / KT)
#define A_HI    0
#define A_LO    16384
#define B_T     32768
#define BUFS    65536
#define ATTN_SMEM (2 * BUFS)

__global__ __launch_bounds__(512) void attn_mma_kernel(
    const int* __restrict__ adj, float* __restrict__ out)
{
    extern __shared__ char smem[];
    __shared__ float den_s[64];
    const uint32_t sb = smem_u32(smem);
    const int t = threadIdx.x, lane = t & 31, wid = t >> 5;
    const int i0 = blockIdx.x * 64;

    // ---- weight-gen mapping: warp rq (16), lane jq (32); rows rq+16u, j jq*4..+3 ----
    const int jq = t & 31, rq = t >> 5;
    float a1r[4], e1pv[4], e1nv[4], den[4];
    const int* adjp[4];
    uint32_t aSts[4];
#pragma unroll
    for (int u = 0; u < 4; u++) {
        int row = rq + 16 * u;
        int gi = i0 + row;
        a1r[u] = g_a1[gi]; e1pv[u] = g_e1p[gi]; e1nv[u] = g_e1n[gi];
        den[u] = 0.f;
        adjp[u] = adj + (size_t)gi * NN + jq * 4;
        aSts[u] = row * 256 + ((jq * 8) ^ ((row & 7) << 4));
    }

    // ---- B cp.async mapping: row bn (=d, 128), quarter bq (64B) ----
    const int bn = t >> 2, bq = t & 3;
    const unsigned short* srcB = g_hTf + (size_t)bn * NN + bq * 32;
    uint32_t bOff[4];
#pragma unroll
    for (int q = 0; q < 4; q++)
        bOff[q] = bn * 256 + (((uint32_t)(bq * 64 + q * 16)) ^ ((bn & 7) << 4));

    // ---- mma mapping ----
    const int team = wid >> 3, w8 = wid & 7;
    const int wm = w8 >> 2, wn = w8 & 3;
    const int s0 = team * 4;
    uint32_t aRowOff[2], bRowOff[2];
#pragma unroll
    for (int m = 0; m < 2; m++)
        aRowOff[m] = (uint32_t)(wm * 32 + m * 16 + (lane & 15)) * 256;
#pragma unroll
    for (int p = 0; p < 2; p++)
        bRowOff[p] = (uint32_t)(wn * 32 + p * 16 + (lane & 7) + ((lane >> 4) << 3)) * 256;
    const uint32_t mXor = (lane & 7) << 4;
    const uint32_t aCol = (lane >> 4) << 4;
    const uint32_t bCol = (lane & 8) << 1;

    float acc[32];
#pragma unroll
    for (int i = 0; i < 32; i++) acc[i] = 0.f;

    // ---- prefetch regs (tile k) ----
    int4 adjR[4]; float4 a2R, epR, enR;
    auto prefetch = [&](int J0) {
#pragma unroll
        for (int u = 0; u < 4; u++) adjR[u] = *(const int4*)(adjp[u] + J0);
        a2R = *(const float4*)&g_a2[J0 + jq * 4];
        epR = *(const float4*)&g_e2p[J0 + jq * 4];
        enR = *(const float4*)&g_e2n[J0 + jq * 4];
    };
    auto cpB = [&](uint32_t bufb, int J0) {
#pragma unroll
        for (int q = 0; q < 4; q++)
            CP16(sb + bufb + B_T + bOff[q], (const void*)(srcB + J0 + q * 8));
        CP_COMMIT();
    };

    // ---- prologue ----
    cpB(0, 0);
    prefetch(0);

    for (int k = 0; k < ITERS; k++) {
        const uint32_t bufb = (k & 1) ? BUFS : 0;
        const uint32_t obufb = BUFS - bufb;

        // ---- compute weights for tile k (registers only) ----
        uint2 whi[4], wlo[4];
        {
            float a2a[4] = {a2R.x, a2R.y, a2R.z, a2R.w};
            float epa[4] = {epR.x, epR.y, epR.z, epR.w};
            float ena[4] = {enR.x, enR.y, enR.z, enR.w};
#pragma unroll
            for (int u = 0; u < 4; u++) {
                int avi[4] = {adjR[u].x, adjR[u].y, adjR[u].z, adjR[u].w};
                float w[4];
#pragma unroll
                for (int q = 0; q < 4; q++) {
                    float ta = a1r[u] + a2a[q];
                    float e1 = (ta >= 0.f) ? e1pv[u] : e1nv[u];
                    float e2 = (ta >= 0.f) ? epa[q] : ena[q];
                    float wq = e1 * e2;
                    wq = avi[q] ? wq : 0.f;
                    den[u] += wq;
                    w[q] = wq;
                }
                __half2 p0 = __floats2half2_rn(w[0], w[1]);
                __half2 p1 = __floats2half2_rn(w[2], w[3]);
                float2 f0 = __half22float2(p0);
                float2 f1 = __half22float2(p1);
                __half2 q0 = __floats2half2_rn(w[0] - f0.x, w[1] - f0.y);
                __half2 q1 = __floats2half2_rn(w[2] - f1.x, w[3] - f1.y);
                whi[u] = make_uint2(*reinterpret_cast<uint32_t*>(&p0),
                                    *reinterpret_cast<uint32_t*>(&p1));
                wlo[u] = make_uint2(*reinterpret_cast<uint32_t*>(&q0),
                                    *reinterpret_cast<uint32_t*>(&q1));
            }
        }

        __syncthreads();   // all reads of bufb (iter k-2) done
#pragma unroll
        for (int u = 0; u < 4; u++) {
            *(uint2*)(smem + bufb + A_HI + aSts[u]) = whi[u];
            *(uint2*)(smem + bufb + A_LO + aSts[u]) = wlo[u];
        }
        CP_WAIT0();        // B(k) arrived
        __syncthreads();

        if (k + 1 < ITERS) cpB(obufb, (k + 1) * KT);

        // ---- mma: this team's 4 k16 steps ----
        const uint32_t ab = sb + bufb;
#pragma unroll
        for (int si = 0; si < 4; si++) {
            const uint32_t cs = (s0 + si) * 32;
            uint32_t ah[2][4], al[2][4], bb[2][4];
            const uint32_t ca = (cs + aCol) ^ mXor;
            const uint32_t cb = (cs + bCol) ^ mXor;
#pragma unroll
            for (int m = 0; m < 2; m++) {
                LDSM4(ah[m][0], ah[m][1], ah[m][2], ah[m][3], ab + A_HI + aRowOff[m] + ca);
                LDSM4(al[m][0], al[m][1], al[m][2], al[m][3], ab + A_LO + aRowOff[m] + ca);
            }
#pragma unroll
            for (int p = 0; p < 2; p++)
                LDSM4(bb[p][0], bb[p][1], bb[p][2], bb[p][3], ab + B_T + bRowOff[p] + cb);
#pragma unroll
            for (int m = 0; m < 2; m++)
#pragma unroll
                for (int nt = 0; nt < 4; nt++) {
                    float* c = &acc[(m * 4 + nt) * 4];
                    uint32_t b0 = bb[nt >> 1][(nt & 1) * 2], b1 = bb[nt >> 1][(nt & 1) * 2 + 1];
                    MMA_F16(c, ah[m], b0, b1);
                    MMA_F16(c, al[m], b0, b1);
                }
        }

        if (k + 1 < ITERS) prefetch((k + 1) * KT);
    }

    // ---- denominator: full-warp reduce (jq = lane) ----
#pragma unroll
    for (int o = 16; o > 0; o >>= 1)
#pragma unroll
        for (int u = 0; u < 4; u++) den[u] += __shfl_xor_sync(0xffffffffu, den[u], o);
    if (lane == 0)
#pragma unroll
        for (int u = 0; u < 4; u++) den_s[rq + 16 * u] = den[u];

    // ---- merge teams ----
    float* out_s = (float*)smem;   // 64 x 130 floats (buffers dead)
    __syncthreads();
    if (team == 1) {
#pragma unroll
        for (int m = 0; m < 2; m++) {
            int r0 = wm * 32 + m * 16 + (lane >> 2);
#pragma unroll
            for (int nt = 0; nt < 4; nt++) {
                float* c = &acc[(m * 4 + nt) * 4];
                int col = wn * 32 + nt * 8 + (lane & 3) * 2;
                *(float2*)&out_s[r0 * 130 + col]       = make_float2(c[0], c[1]);
                *(float2*)&out_s[(r0 + 8) * 130 + col] = make_float2(c[2], c[3]);
            }
        }
    }
    __syncthreads();
    if (team == 0) {
#pragma unroll
        for (int m = 0; m < 2; m++) {
            int r0 = wm * 32 + m * 16 + (lane >> 2);
            float inv0 = 1.0f / den_s[r0];
            float inv1 = 1.0f / den_s[r0 + 8];
#pragma unroll
            for (int nt = 0; nt < 4; nt++) {
                float* c = &acc[(m * 4 + nt) * 4];
                int col = wn * 32 + nt * 8 + (lane & 3) * 2;
                float2 p0 = *(const float2*)&out_s[r0 * 130 + col];
                float2 p1 = *(const float2*)&out_s[(r0 + 8) * 130 + col];
                *(float2*)&out[(size_t)(i0 + r0) * DOUT + col] =
                    make_float2((c[0] + p0.x) * inv0, (c[1] + p0.y) * inv0);
                *(float2*)&out[(size_t)(i0 + r0 + 8) * DOUT + col] =
                    make_float2((c[2] + p1.x) * inv1, (c[3] + p1.y) * inv1);
            }
        }
    }
}

// ============================================================
extern "C" void kernel_launch(void* const* d_in, const int* in_sizes, int n_in,
                              void* d_out, int out_size)
{
    const float* feat = (const float*)d_in[0];
    const int*   adj  = (const int*)d_in[1];
    const float* W    = (const float*)d_in[2];
    const float* b    = (const float*)d_in[3];
    const float* w1   = (const float*)d_in[4];
    const float* b1   = (const float*)d_in[5];
    const float* w2   = (const float*)d_in[6];
    const float* b2   = (const float*)d_in[7];
    float* out = (float*)d_out;

    static bool attr_set = false;
    if (!attr_set) {
        cudaFuncSetAttribute(attn_mma_kernel,
                             cudaFuncAttributeMaxDynamicSharedMemorySize, ATTN_SMEM);
        attr_set = true;
    }

    gemm_h_kernel<<<NN / 64, 256>>>(feat, W, b);
    prep_kernel<<<NN / 8, 256>>>(w1, b1, w2, b2);
    convert_hT_kernel<<<dim3(NN / 32, DOUT / 32), 256>>>();
    attn_mma_kernel<<<NN / 64, 512, ATTN_SMEM>>>(adj, out);
}

// round 7
// speedup vs baseline: 2.4050x; 1.1434x over previous
#include <cuda_runtime.h>
#include <cuda_fp16.h>
#include <math.h>
#include <cstdint>

#define NN   8192
#define DIN  256
#define DOUT 128

// ---------------- scratch ----------------
__device__ float g_h[NN * DOUT];                 // 4 MB fp32 h
__device__ float g_a1[NN], g_a2[NN];
__device__ float g_e1p[NN], g_e1n[NN];           // exp(a1), exp(0.01*a1)
__device__ float g_e2p[NN], g_e2n[NN];           // exp(a2), exp(0.01*a2)
__device__ unsigned short g_hTf[DOUT * NN];      // fp16 hT [d][j]

// ---------------- helpers ----------------
__device__ __forceinline__ uint32_t smem_u32(const void* p) {
    uint32_t a;
    asm("{ .reg .u64 t; cvta.to.shared.u64 t, %1; cvt.u32.u64 %0, t; }" : "=r"(a) : "l"(p));
    return a;
}
#define LDSM4(r0, r1, r2, r3, addr)                                            \
    asm volatile("ldmatrix.sync.aligned.m8n8.x4.shared.b16 {%0,%1,%2,%3}, [%4];" \
        : "=r"(r0), "=r"(r1), "=r"(r2), "=r"(r3) : "r"(addr))
#define MMA_F16(c, a, b0, b1)                                                  \
    asm volatile("mma.sync.aligned.m16n8k16.row.col.f32.f16.f16.f32 "          \
        "{%0,%1,%2,%3},{%4,%5,%6,%7},{%8,%9},{%0,%1,%2,%3};"                   \
        : "+f"((c)[0]), "+f"((c)[1]), "+f"((c)[2]), "+f"((c)[3])               \
        : "r"((a)[0]), "r"((a)[1]), "r"((a)[2]), "r"((a)[3]), "r"(b0), "r"(b1))
#define CP16(dst, src)                                                         \
    asm volatile("cp.async.ca.shared.global [%0], [%1], 16;"                   \
        :: "r"(dst), "l"(src) : "memory")
#define CP_COMMIT() asm volatile("cp.async.commit_group;" ::: "memory")
#define CP_WAIT0()  asm volatile("cp.async.wait_group 0;" ::: "memory")

// ============================================================
// Kernel 1: h = feat @ W^T + b
// ============================================================
__global__ __launch_bounds__(256) void gemm_h_kernel(
    const float* __restrict__ feat, const float* __restrict__ W, const float* __restrict__ bias)
{
    __shared__ float fs[64][32];
    __shared__ float ws[32][132];
    const int t = threadIdx.x;
    const int i0 = blockIdx.x * 64;
    const int ty = t >> 4, tx = t & 15;
    float acc[4][8];
#pragma unroll
    for (int r = 0; r < 4; r++)
#pragma unroll
        for (int c = 0; c < 8; c++) acc[r][c] = 0.f;

    for (int k0 = 0; k0 < DIN; k0 += 32) {
#pragma unroll
        for (int v = 0; v < 2; v++) {
            int f = v * 256 + t, row = f >> 3, off = (f & 7) * 4;
            *(float4*)&fs[row][off] = *(const float4*)&feat[(size_t)(i0 + row) * DIN + k0 + off];
        }
        {
            int c = t >> 1, half = (t & 1) * 16;
#pragma unroll
            for (int q = 0; q < 4; q++) {
                float4 wv = *(const float4*)&W[(size_t)c * DIN + k0 + half + q * 4];
                ws[half + q * 4 + 0][c] = wv.x; ws[half + q * 4 + 1][c] = wv.y;
                ws[half + q * 4 + 2][c] = wv.z; ws[half + q * 4 + 3][c] = wv.w;
            }
        }
        __syncthreads();
#pragma unroll
        for (int kk = 0; kk < 32; kk++) {
            float a[4];
#pragma unroll
            for (int r = 0; r < 4; r++) a[r] = fs[ty * 4 + r][kk];
            float4 b0 = *(const float4*)&ws[kk][tx * 8];
            float4 b1 = *(const float4*)&ws[kk][tx * 8 + 4];
            float bb[8] = {b0.x, b0.y, b0.z, b0.w, b1.x, b1.y, b1.z, b1.w};
#pragma unroll
            for (int r = 0; r < 4; r++)
#pragma unroll
                for (int c = 0; c < 8; c++) acc[r][c] += a[r] * bb[c];
        }
        __syncthreads();
    }
#pragma unroll
    for (int r = 0; r < 4; r++) {
        int gi = i0 + ty * 4 + r;
#pragma unroll
        for (int c = 0; c < 8; c++)
            g_h[(size_t)gi * DOUT + tx * 8 + c] = acc[r][c] + bias[tx * 8 + c];
    }
}

// ============================================================
// Kernel 2: a1,a2 + factorized exp tables
// ============================================================
__global__ __launch_bounds__(256) void prep_kernel(
    const float* __restrict__ w1, const float* __restrict__ b1,
    const float* __restrict__ w2, const float* __restrict__ b2)
{
    const int warp = threadIdx.x >> 5, lane = threadIdx.x & 31;
    const int i = blockIdx.x * 8 + warp;
    float s1 = 0.f, s2 = 0.f;
#pragma unroll
    for (int d = lane; d < DOUT; d += 32) {
        float hv = g_h[(size_t)i * DOUT + d];
        s1 += hv * w1[d]; s2 += hv * w2[d];
    }
#pragma unroll
    for (int o = 16; o > 0; o >>= 1) {
        s1 += __shfl_xor_sync(0xffffffffu, s1, o);
        s2 += __shfl_xor_sync(0xffffffffu, s2, o);
    }
    if (lane == 0) {
        float a1 = s1 + b1[0], a2 = s2 + b2[0];
        g_a1[i] = a1; g_a2[i] = a2;
        g_e1p[i] = expf(a1); g_e1n[i] = expf(0.01f * a1);
        g_e2p[i] = expf(a2); g_e2n[i] = expf(0.01f * a2);
    }
}

// ============================================================
// Kernel 3: transpose h -> fp16 hT [d][j]
// ============================================================
__global__ __launch_bounds__(256) void convert_hT_kernel()
{
    __shared__ float s[32][33];
    const int i0 = blockIdx.x * 32, d0 = blockIdx.y * 32;
    const int lx = threadIdx.x & 31, ly = threadIdx.x >> 5;
#pragma unroll
    for (int q = 0; q < 4; q++) {
        int il = ly + q * 8;
        s[il][lx] = g_h[(size_t)(i0 + il) * DOUT + d0 + lx];
    }
    __syncthreads();
#pragma unroll
    for (int q = 0; q < 4; q++) {
        int dl = ly + q * 8;
        __half hv = __float2half_rn(s[lx][dl]);
        g_hTf[(size_t)(d0 + dl) * NN + i0 + lx] = *reinterpret_cast<unsigned short*>(&hv);
    }
}

// ============================================================
// Kernel 4: fused attention, single fp16 product, KT=128, 512 thr
// 128 blocks; CTA M=64 x N=128. 16 warps = 2 k-teams x (2m x 4n),
// team0 ksteps 0-3, team1 ksteps 4-7.
// SMEM/buffer: A 16K | B 32K = 48K; x2 = 96K
// ============================================================
#define KT      128
#define ITERS   (NN / KT)
#define A_T     0
#define B_T     16384
#define BUFS    49152
#define ATTN_SMEM (2 * BUFS)

__global__ __launch_bounds__(512) void attn_mma_kernel(
    const int* __restrict__ adj, float* __restrict__ out)
{
    extern __shared__ char smem[];
    __shared__ float den_s[64];
    const uint32_t sb = smem_u32(smem);
    const int t = threadIdx.x, lane = t & 31, wid = t >> 5;
    const int i0 = blockIdx.x * 64;

    // ---- weight-gen mapping: warp rq (16), lane jq (32); rows rq+16u, j jq*4..+3 ----
    const int jq = t & 31, rq = t >> 5;
    float a1r[4], e1pv[4], e1nv[4], den[4];
    const int* adjp[4];
    uint32_t aSts[4];
#pragma unroll
    for (int u = 0; u < 4; u++) {
        int row = rq + 16 * u;
        int gi = i0 + row;
        a1r[u] = g_a1[gi]; e1pv[u] = g_e1p[gi]; e1nv[u] = g_e1n[gi];
        den[u] = 0.f;
        adjp[u] = adj + (size_t)gi * NN + jq * 4;
        aSts[u] = row * 256 + ((jq * 8) ^ ((row & 7) << 4));
    }

    // ---- B cp.async mapping: row bn (=d, 128), quarter bq (64B) ----
    const int bn = t >> 2, bq = t & 3;
    const unsigned short* srcB = g_hTf + (size_t)bn * NN + bq * 32;
    uint32_t bOff[4];
#pragma unroll
    for (int q = 0; q < 4; q++)
        bOff[q] = bn * 256 + (((uint32_t)(bq * 64 + q * 16)) ^ ((bn & 7) << 4));

    // ---- mma mapping ----
    const int team = wid >> 3, w8 = wid & 7;
    const int wm = w8 >> 2, wn = w8 & 3;
    const int s0 = team * 4;
    uint32_t aRowOff[2], bRowOff[2];
#pragma unroll
    for (int m = 0; m < 2; m++)
        aRowOff[m] = (uint32_t)(wm * 32 + m * 16 + (lane & 15)) * 256;
#pragma unroll
    for (int p = 0; p < 2; p++)
        bRowOff[p] = (uint32_t)(wn * 32 + p * 16 + (lane & 7) + ((lane >> 4) << 3)) * 256;
    const uint32_t mXor = (lane & 7) << 4;
    const uint32_t aCol = (lane >> 4) << 4;
    const uint32_t bCol = (lane & 8) << 1;

    float acc[32];
#pragma unroll
    for (int i = 0; i < 32; i++) acc[i] = 0.f;

    // ---- prefetch regs (tile k) ----
    int4 adjR[4]; float4 a2R, epR, enR;
    auto prefetch = [&](int J0) {
#pragma unroll
        for (int u = 0; u < 4; u++) adjR[u] = *(const int4*)(adjp[u] + J0);
        a2R = *(const float4*)&g_a2[J0 + jq * 4];
        epR = *(const float4*)&g_e2p[J0 + jq * 4];
        enR = *(const float4*)&g_e2n[J0 + jq * 4];
    };
    auto cpB = [&](uint32_t bufb, int J0) {
#pragma unroll
        for (int q = 0; q < 4; q++)
            CP16(sb + bufb + B_T + bOff[q], (const void*)(srcB + J0 + q * 8));
        CP_COMMIT();
    };

    // ---- prologue ----
    cpB(0, 0);
    prefetch(0);

    for (int k = 0; k < ITERS; k++) {
        const uint32_t bufb = (k & 1) ? BUFS : 0;
        const uint32_t obufb = BUFS - bufb;

        // ---- compute weights for tile k (registers only) ----
        uint2 whi[4];
        {
            float a2a[4] = {a2R.x, a2R.y, a2R.z, a2R.w};
            float epa[4] = {epR.x, epR.y, epR.z, epR.w};
            float ena[4] = {enR.x, enR.y, enR.z, enR.w};
#pragma unroll
            for (int u = 0; u < 4; u++) {
                int avi[4] = {adjR[u].x, adjR[u].y, adjR[u].z, adjR[u].w};
                float w[4];
#pragma unroll
                for (int q = 0; q < 4; q++) {
                    float ta = a1r[u] + a2a[q];
                    float e1 = (ta >= 0.f) ? e1pv[u] : e1nv[u];
                    float e2 = (ta >= 0.f) ? epa[q] : ena[q];
                    float wq = e1 * e2;
                    wq = avi[q] ? wq : 0.f;
                    den[u] += wq;
                    w[q] = wq;
                }
                __half2 p0 = __floats2half2_rn(w[0], w[1]);
                __half2 p1 = __floats2half2_rn(w[2], w[3]);
                whi[u] = make_uint2(*reinterpret_cast<uint32_t*>(&p0),
                                    *reinterpret_cast<uint32_t*>(&p1));
            }
        }

        __syncthreads();   // all reads of bufb (iter k-2) done
#pragma unroll
        for (int u = 0; u < 4; u++)
            *(uint2*)(smem + bufb + A_T + aSts[u]) = whi[u];
        CP_WAIT0();        // B(k) arrived
        __syncthreads();

        if (k + 1 < ITERS) cpB(obufb, (k + 1) * KT);

        // ---- mma: this team's 4 k16 steps ----
        const uint32_t ab = sb + bufb;
#pragma unroll
        for (int si = 0; si < 4; si++) {
            const uint32_t cs = (s0 + si) * 32;
            uint32_t aa[2][4], bb[2][4];
            const uint32_t ca = (cs + aCol) ^ mXor;
            const uint32_t cb = (cs + bCol) ^ mXor;
#pragma unroll
            for (int m = 0; m < 2; m++)
                LDSM4(aa[m][0], aa[m][1], aa[m][2], aa[m][3], ab + A_T + aRowOff[m] + ca);
#pragma unroll
            for (int p = 0; p < 2; p++)
                LDSM4(bb[p][0], bb[p][1], bb[p][2], bb[p][3], ab + B_T + bRowOff[p] + cb);
#pragma unroll
            for (int m = 0; m < 2; m++)
#pragma unroll
                for (int nt = 0; nt < 4; nt++) {
                    float* c = &acc[(m * 4 + nt) * 4];
                    uint32_t b0 = bb[nt >> 1][(nt & 1) * 2], b1 = bb[nt >> 1][(nt & 1) * 2 + 1];
                    MMA_F16(c, aa[m], b0, b1);
                }
        }

        if (k + 1 < ITERS) prefetch((k + 1) * KT);
    }

    // ---- denominator: full-warp reduce (jq = lane) ----
#pragma unroll
    for (int o = 16; o > 0; o >>= 1)
#pragma unroll
        for (int u = 0; u < 4; u++) den[u] += __shfl_xor_sync(0xffffffffu, den[u], o);
    if (lane == 0)
#pragma unroll
        for (int u = 0; u < 4; u++) den_s[rq + 16 * u] = den[u];

    // ---- merge teams ----
    float* out_s = (float*)smem;   // 64 x 130 floats (buffers dead)
    __syncthreads();
    if (team == 1) {
#pragma unroll
        for (int m = 0; m < 2; m++) {
            int r0 = wm * 32 + m * 16 + (lane >> 2);
#pragma unroll
            for (int nt = 0; nt < 4; nt++) {
                float* c = &acc[(m * 4 + nt) * 4];
                int col = wn * 32 + nt * 8 + (lane & 3) * 2;
                *(float2*)&out_s[r0 * 130 + col]       = make_float2(c[0], c[1]);
                *(float2*)&out_s[(r0 + 8) * 130 + col] = make_float2(c[2], c[3]);
            }
        }
    }
    __syncthreads();
    if (team == 0) {
#pragma unroll
        for (int m = 0; m < 2; m++) {
            int r0 = wm * 32 + m * 16 + (lane >> 2);
            float inv0 = 1.0f / den_s[r0];
            float inv1 = 1.0f / den_s[r0 + 8];
#pragma unroll
            for (int nt = 0; nt < 4; nt++) {
                float* c = &acc[(m * 4 + nt) * 4];
                int col = wn * 32 + nt * 8 + (lane & 3) * 2;
                float2 p0 = *(const float2*)&out_s[r0 * 130 + col];
                float2 p1 = *(const float2*)&out_s[(r0 + 8) * 130 + col];
                *(float2*)&out[(size_t)(i0 + r0) * DOUT + col] =
                    make_float2((c[0] + p0.x) * inv0, (c[1] + p0.y) * inv0);
                *(float2*)&out[(size_t)(i0 + r0 + 8) * DOUT + col] =
                    make_float2((c[2] + p1.x) * inv1, (c[3] + p1.y) * inv1);
            }
        }
    }
}

// ============================================================
extern "C" void kernel_launch(void* const* d_in, const int* in_sizes, int n_in,
                              void* d_out, int out_size)
{
    const float* feat = (const float*)d_in[0];
    const int*   adj  = (const int*)d_in[1];
    const float* W    = (const float*)d_in[2];
    const float* b    = (const float*)d_in[3];
    const float* w1   = (const float*)d_in[4];
    const float* b1   = (const float*)d_in[5];
    const float* w2   = (const float*)d_in[6];
    const float* b2   = (const float*)d_in[7];
    float* out = (float*)d_out;

    static bool attr_set = false;
    if (!attr_set) {
        cudaFuncSetAttribute(attn_mma_kernel,
                             cudaFuncAttributeMaxDynamicSharedMemorySize, ATTN_SMEM);
        attr_set = true;
    }

    gemm_h_kernel<<<NN / 64, 256>>>(feat, W, b);
    prep_kernel<<<NN / 8, 256>>>(w1, b1, w2, b2);
    convert_hT_kernel<<<dim3(NN / 32, DOUT / 32), 256>>>();
    attn_mma_kernel<<<NN / 64, 512, ATTN_SMEM>>>(adj, out);
}